// round 3
// baseline (speedup 1.0000x reference)
#include <cuda_runtime.h>
#include <cstdint>

// Problem constants
#define BQ 1024
#define TT 365
#define DD 5
#define SS 27
#define HH 256

// Tiling
#define BT   64    // batch rows per group
#define HC   32    // h-columns per CTA (per gate)
#define GROUPS 16  // batch groups (1024/64)
#define CPG    8   // CTAs per group (256/32)
#define NCTA 128
#define NTHR 256

// Global state (allocation-free scratch)
__device__ float    g_h[2][BQ][HH];          // double-buffered hidden state
__device__ unsigned g_cnt[GROUPS * 32];       // padded barrier counters (128B stride)
__device__ unsigned g_done[GROUPS * 32];      // end-of-kernel reset coordination

// ---- packed fp32x2 helpers (Blackwell FFMA2: 2x fp32 throughput) ----
__device__ __forceinline__ unsigned long long pack2(float lo, float hi) {
    unsigned long long r;
    asm("mov.b64 %0, {%1,%2};" : "=l"(r) : "f"(lo), "f"(hi));
    return r;
}
__device__ __forceinline__ void unpack2(unsigned long long v, float &lo, float &hi) {
    asm("mov.b64 {%0,%1}, %2;" : "=f"(lo), "=f"(hi) : "l"(v));
}
__device__ __forceinline__ void ffma2(unsigned long long &d,
                                      unsigned long long a,
                                      unsigned long long b) {
    asm("fma.rn.f32x2 %0, %1, %2, %0;" : "+l"(d) : "l"(a), "l"(b));
}

__device__ __forceinline__ float sigmoidf_(float x) {
    return 1.f / (1.f + __expf(-x));
}
__device__ __forceinline__ float tanhf_(float x) {
    float e = __expf(-2.f * fabsf(x));   // e in (0,1], no overflow
    float r = (1.f - e) / (1.f + e);
    return copysignf(r, x);
}

// Barrier among the 8 CTAs of one batch group. Monotonic counter (no reset
// during the run); all threads fence so every thread's global stores are
// visible at GPU scope before the arrival is published.
__device__ __forceinline__ void group_barrier(int bi, unsigned phase) {
    __threadfence();
    __syncthreads();
    if (threadIdx.x == 0) {
        atomicAdd(&g_cnt[bi * 32], 1u);
        while (atomicAdd(&g_cnt[bi * 32], 0u) < (unsigned)CPG * phase)
            __nanosleep(32);
    }
    __syncthreads();
}

__global__ __launch_bounds__(NTHR, 1)
void ealstm_kernel(const float* __restrict__ x_dyn,  const float* __restrict__ x_stat,
                   const float* __restrict__ W_i,    const float* __restrict__ b_i,
                   const float* __restrict__ W_f,    const float* __restrict__ b_f,
                   const float* __restrict__ W_g,    const float* __restrict__ b_g,
                   const float* __restrict__ W_o,    const float* __restrict__ b_o,
                   const float* __restrict__ W_head, const float* __restrict__ b_head,
                   float* __restrict__ out)
{
    const int bi   = blockIdx.x >> 3;     // batch group 0..15
    const int cj   = blockIdx.x & 7;      // column tile 0..7
    const int tid  = threadIdx.x;
    const int col  = tid & 31;            // local h-column
    const int rg   = tid >> 5;            // warp id = row group (8 rows each)
    const int row0 = bi * BT;             // first global batch row
    const int colg = cj * HC + col;       // global h column

    // SMEM: h tile [64][256] as float4[64][64], then 3 weight slices
    // k-major float4[64 kq][32 col] each (loaded once, resident all steps).
    extern __shared__ float4 smem4[];
    float4* hs4 = smem4;                  // 64 KB
    float4* wf4 = hs4 + BT * 64;          // 32 KB
    float4* wg4 = wf4 + 64 * HC;          // 32 KB
    float4* wo4 = wg4 + 64 * HC;          // 32 KB

    // ---- one-time: recurrent weight slices -> SMEM (k-major) ----
    for (int e = tid; e < 64 * HC; e += NTHR) {
        const int kq = e >> 5, cc = e & 31;
        const int base = (cj * HC + cc) * (DD + HH) + DD + 4 * kq;
        wf4[kq * HC + cc] = make_float4(W_f[base], W_f[base+1], W_f[base+2], W_f[base+3]);
        wg4[kq * HC + cc] = make_float4(W_g[base], W_g[base+1], W_g[base+2], W_g[base+3]);
        wo4[kq * HC + cc] = make_float4(W_o[base], W_o[base+1], W_o[base+2], W_o[base+3]);
    }
    __syncthreads();

    // ---- per-thread constants in registers ----
    float wxf[DD], wxg[DD], wxo[DD];
#pragma unroll
    for (int d = 0; d < DD; d++) {
        wxf[d] = __ldg(&W_f[colg * (DD + HH) + d]);
        wxg[d] = __ldg(&W_g[colg * (DD + HH) + d]);
        wxo[d] = __ldg(&W_o[colg * (DD + HH) + d]);
    }
    const float bf_ = __ldg(&b_f[colg]);
    const float bg_ = __ldg(&b_g[colg]);
    const float bo_ = __ldg(&b_o[colg]);

    // static input gate + cell state, 8 (row,col) cells per thread
    float ig[8], cst[8];
    {
        const float bi_ = __ldg(&b_i[colg]);
#pragma unroll
        for (int j = 0; j < 8; j++) {
            const int r = row0 + rg * 8 + j;
            float s = bi_;
            for (int ss = 0; ss < SS; ss++)
                s = fmaf(__ldg(&x_stat[r * SS + ss]), __ldg(&W_i[colg * SS + ss]), s);
            ig[j]  = sigmoidf_(s);
            cst[j] = 0.f;
        }
    }

    // ---- recurrence ----
    unsigned phase = 0;
    for (int t = 0; t < TT; t++) {
        if (t > 0) {
            phase++;
            group_barrier(bi, phase);
            // stage h tile (L2-coherent) into SMEM
            const float4* src = reinterpret_cast<const float4*>(&g_h[(t - 1) & 1][row0][0]);
            for (int e = tid; e < BT * 64; e += NTHR)
                hs4[e] = __ldcg(src + e);
            __syncthreads();
        }

        // accumulators, even/odd k lanes packed; init with bias + x-projection
        unsigned long long aF[8], aG[8], aO[8];
        {
            const float* xb = x_dyn + (size_t)(row0 + rg * 8) * (TT * DD) + t * DD;
#pragma unroll
            for (int j = 0; j < 8; j++) {
                const float* xp = xb + (size_t)j * (TT * DD);
                const float x0 = __ldg(xp+0), x1 = __ldg(xp+1), x2 = __ldg(xp+2),
                            x3 = __ldg(xp+3), x4 = __ldg(xp+4);
                float pf = bf_, pg = bg_, po = bo_;
                pf = fmaf(x0,wxf[0],pf); pf = fmaf(x1,wxf[1],pf); pf = fmaf(x2,wxf[2],pf);
                pf = fmaf(x3,wxf[3],pf); pf = fmaf(x4,wxf[4],pf);
                pg = fmaf(x0,wxg[0],pg); pg = fmaf(x1,wxg[1],pg); pg = fmaf(x2,wxg[2],pg);
                pg = fmaf(x3,wxg[3],pg); pg = fmaf(x4,wxg[4],pg);
                po = fmaf(x0,wxo[0],po); po = fmaf(x1,wxo[1],po); po = fmaf(x2,wxo[2],po);
                po = fmaf(x3,wxo[3],po); po = fmaf(x4,wxo[4],po);
                aF[j] = pack2(pf, 0.f);
                aG[j] = pack2(pg, 0.f);
                aO[j] = pack2(po, 0.f);
            }
        }

        if (t > 0) {
            // 64x96x256 tile GEMM: lane=col (conflict-free weight LDS),
            // h rows broadcast. FFMA2 packs (even k, odd k).
#pragma unroll 2
            for (int kq = 0; kq < 64; kq++) {
                const ulonglong2 wfv = *reinterpret_cast<const ulonglong2*>(&wf4[kq * HC + col]);
                const ulonglong2 wgv = *reinterpret_cast<const ulonglong2*>(&wg4[kq * HC + col]);
                const ulonglong2 wov = *reinterpret_cast<const ulonglong2*>(&wo4[kq * HC + col]);
#pragma unroll
                for (int j = 0; j < 8; j++) {
                    const ulonglong2 hv =
                        *reinterpret_cast<const ulonglong2*>(&hs4[(rg * 8 + j) * 64 + kq]);
                    ffma2(aF[j], hv.x, wfv.x); ffma2(aF[j], hv.y, wfv.y);
                    ffma2(aG[j], hv.x, wgv.x); ffma2(aG[j], hv.y, wgv.y);
                    ffma2(aO[j], hv.x, wov.x); ffma2(aO[j], hv.y, wov.y);
                }
            }
        }

        // epilogue: gates, cell update, write h slice (L2-coherent)
        const int wb = t & 1;
#pragma unroll
        for (int j = 0; j < 8; j++) {
            float lo, hi;
            unpack2(aF[j], lo, hi); const float f = sigmoidf_(lo + hi);
            unpack2(aG[j], lo, hi); const float g = tanhf_(lo + hi);
            unpack2(aO[j], lo, hi); const float o = sigmoidf_(lo + hi);
            const float cn = fmaf(f, cst[j], ig[j] * g);
            cst[j] = cn;
            const float hv = o * tanhf_(cn);
            __stcg(&g_h[wb][row0 + rg * 8 + j][colg], hv);
        }
    }

    // ---- head: out[b] = h_T[b] . W_head + b_head ----
    phase++;
    group_barrier(bi, phase);
    if (cj == 0) {
        const int row  = tid >> 2, part = tid & 3;
        const int r    = row0 + row;
        const float* hp = &g_h[(TT - 1) & 1][r][0];
        float s = 0.f;
        for (int k = part * 64; k < part * 64 + 64; k++)
            s = fmaf(__ldcg(hp + k), __ldg(&W_head[k]), s);
        s += __shfl_xor_sync(0xffffffffu, s, 1);
        s += __shfl_xor_sync(0xffffffffu, s, 2);
        if (part == 0) out[r] = s + __ldg(&b_head[0]);
    }

    // ---- reset barrier counters so graph replays are deterministic ----
    __syncthreads();
    if (tid == 0) {
        __threadfence();
        atomicAdd(&g_done[bi * 32], 1u);
        if (cj == 0) {
            while (atomicAdd(&g_done[bi * 32], 0u) < CPG) __nanosleep(64);
            atomicExch(&g_cnt[bi * 32], 0u);
            atomicExch(&g_done[bi * 32], 0u);
        }
    }
}

extern "C" void kernel_launch(void* const* d_in, const int* in_sizes, int n_in,
                              void* d_out, int out_size) {
    (void)in_sizes; (void)n_in; (void)out_size;
    const size_t smem_bytes = (size_t)(BT * 64 + 3 * 64 * HC) * sizeof(float4); // 160 KB
    cudaFuncSetAttribute(ealstm_kernel,
                         cudaFuncAttributeMaxDynamicSharedMemorySize,
                         (int)smem_bytes);
    ealstm_kernel<<<NCTA, NTHR, smem_bytes>>>(
        (const float*)d_in[0],  (const float*)d_in[1],
        (const float*)d_in[2],  (const float*)d_in[3],
        (const float*)d_in[4],  (const float*)d_in[5],
        (const float*)d_in[6],  (const float*)d_in[7],
        (const float*)d_in[8],  (const float*)d_in[9],
        (const float*)d_in[10], (const float*)d_in[11],
        (float*)d_out);
}